// round 6
// baseline (speedup 1.0000x reference)
#include <cuda_runtime.h>
#include <cuda_bf16.h>
#include <math_constants.h>
#include <cstdint>

// Problem dims (fixed by setup_inputs)
constexpr int NP = 32768;   // 8*4096 points
constexpr int KC = 2048;    // codebook size
constexpr int D  = 128;     // dim
constexpr float TEMP_INV = 1.0f / 0.9f;
constexpr float LEPS = 1e-6f;
constexpr float RESCUE_THR = 1e-2f;   // approx-score margin for exact rescoring

// Scratch (__device__ globals; no allocation allowed)
__device__ float g_scores[(size_t)NP * KC];            // 256 MB score matrix
__device__ float g_esq[KC];                            // ||e_k||^2
__device__ __nv_bfloat16 g_Xs[(size_t)NP * 256];       // 2-way bf16 split of x
__device__ __nv_bfloat16 g_Es[(size_t)KC * 256];       // 2-way bf16 split of embed
__device__ float g_part[(size_t)(NP / 32) * KC];       // per-block class-prob partials
__device__ float g_part2[16 * KC];                     // stage-1 reduced partials
__device__ float g_acc[KC];                            // class sums

// ---------------------------------------------------------------------------
__device__ __forceinline__ uint32_t smem_u32(const void* p) {
    uint32_t a;
    asm("{ .reg .u64 t; cvta.to.shared.u64 t, %1; cvt.u32.u64 %0, t; }" : "=r"(a) : "l"(p));
    return a;
}
__device__ __forceinline__ uint32_t sw128(uint32_t off) { return off ^ ((off >> 3) & 0x70); }

__device__ __forceinline__ void cp_async16(uint32_t saddr, const void* gaddr) {
    asm volatile("cp.async.cg.shared.global [%0], [%1], 16;" :: "r"(saddr), "l"(gaddr));
}
#define CP_COMMIT() asm volatile("cp.async.commit_group;" ::: "memory")
#define CP_WAIT(n)  asm volatile("cp.async.wait_group %0;" :: "n"(n) : "memory")

__device__ __forceinline__ void ldm_x4(uint32_t* a, uint32_t addr) {
    asm volatile("ldmatrix.sync.aligned.m8n8.x4.shared.b16 {%0,%1,%2,%3}, [%4];"
                 : "=r"(a[0]), "=r"(a[1]), "=r"(a[2]), "=r"(a[3]) : "r"(addr));
}
__device__ __forceinline__ void mma_bf16(float* c, const uint32_t* a, const uint32_t* b) {
    asm volatile("mma.sync.aligned.m16n8k16.row.col.f32.bf16.bf16.f32 "
                 "{%0,%1,%2,%3}, {%4,%5,%6,%7}, {%8,%9}, {%0,%1,%2,%3};"
                 : "+f"(c[0]), "+f"(c[1]), "+f"(c[2]), "+f"(c[3])
                 : "r"(a[0]), "r"(a[1]), "r"(a[2]), "r"(a[3]), "r"(b[0]), "r"(b[1]));
}

// ---------------------------------------------------------------------------
// Kernel 0: 2-way bf16 split of x and embed
// ---------------------------------------------------------------------------
__global__ __launch_bounds__(256) void split_kernel(const float* __restrict__ x,
                                                    const float* __restrict__ e) {
    int i = blockIdx.x * 256 + threadIdx.x;
    float v; __nv_bfloat16* dst; int c;
    if (i < NP * D) {
        v = x[i]; c = i & (D - 1);
        dst = g_Xs + (size_t)(i >> 7) * 256;
    } else {
        int j = i - NP * D;
        if (j >= KC * D) return;
        v = e[j]; c = j & (D - 1);
        dst = g_Es + (size_t)(j >> 7) * 256;
    }
    __nv_bfloat16 b0 = __float2bfloat16(v);
    float r1 = v - __bfloat162float(b0);
    __nv_bfloat16 b1 = __float2bfloat16(r1);
    dst[c] = b0; dst[128 + c] = b1;
}

// ---------------------------------------------------------------------------
// Kernel 1: e_sq
// ---------------------------------------------------------------------------
__global__ void prep_kernel(const float* __restrict__ embed) {
    int k = blockIdx.x * blockDim.x + threadIdx.x;
    if (k < KC) {
        const float4* e = (const float4*)(embed + (size_t)k * D);
        float s = 0.f;
#pragma unroll
        for (int i = 0; i < D / 4; i++) {
            float4 v = e[i];
            s += v.x * v.x + v.y * v.y + v.z * v.z + v.w * v.w;
        }
        g_esq[k] = s;
    }
}

// ---------------------------------------------------------------------------
// Kernel 2: mma.sync bf16 GEMM  S = 2*(X*E^T via 3 split-products) - e_sq
// 128 threads (4 warps), block tile M128 x N128, warp tile 64x64.
// 6 K-chunks of 64 (virtual K=384), double-buffered cp.async.
// ---------------------------------------------------------------------------
constexpr int STG_SZ = 128 * 128;                 // 16 KB per operand stage
constexpr int GEMM_SMEM = 128 * 129 * 4;          // 66048 B (>= 4*STG_SZ)

__constant__ int c_PA[3] = {0, 0, 1};
__constant__ int c_PB[3] = {0, 1, 0};

__global__ __launch_bounds__(128, 2) void gemm_kernel() {
    extern __shared__ char smem[];
    const uint32_t sb = smem_u32(smem);
    const int tid = threadIdx.x, wid = tid >> 5, lane = tid & 31;
    const int wm = wid >> 1, wn = wid & 1;       // warp 64x64 tile
    const int bm = blockIdx.y * 128, bn = blockIdx.x * 128;

    float acc[4][8][4];
#pragma unroll
    for (int mt = 0; mt < 4; mt++)
#pragma unroll
        for (int nt = 0; nt < 8; nt++)
#pragma unroll
            for (int q = 0; q < 4; q++) acc[mt][nt][q] = 0.f;

    // ldmatrix lane-address components
    const int a_lrow = (lane & 7) + ((lane >> 3) & 1) * 8;     // A x4
    const int a_lcol = ((lane >> 4) & 1) * 16;
    const int b_lrow = ((lane >> 4) & 1) * 8 + (lane & 7);     // B x4 (2 n-tiles)
    const int b_lcol = ((lane >> 3) & 1) * 16;

    // loader: one 128B row per thread per operand (8 x 16B)
    auto issue_chunk = [&](int c, int stage) {
        const int p = c >> 1, h = c & 1;
        const int aoff = c_PA[p] * 128 + h * 64;
        const int boff = c_PB[p] * 128 + h * 64;
        const uint32_t sa = sb + stage * 2 * STG_SZ;
        const uint32_t sbB = sa + STG_SZ;
        const __nv_bfloat16* ga = g_Xs + (size_t)(bm + tid) * 256 + aoff;
        const __nv_bfloat16* gb = g_Es + (size_t)(bn + tid) * 256 + boff;
#pragma unroll
        for (int s = 0; s < 8; s++) {
            cp_async16(sa + sw128((uint32_t)tid * 128 + s * 16), ga + s * 8);
            cp_async16(sbB + sw128((uint32_t)tid * 128 + s * 16), gb + s * 8);
        }
        CP_COMMIT();
    };

    issue_chunk(0, 0);

#pragma unroll 1
    for (int c = 0; c < 6; c++) {
        const int stage = c & 1;
        if (c < 5) {
            issue_chunk(c + 1, stage ^ 1);
            CP_WAIT(1);
        } else {
            CP_WAIT(0);
        }
        __syncthreads();

        const uint32_t sa = sb + stage * 2 * STG_SZ;
        const uint32_t sbB = sa + STG_SZ;
#pragma unroll
        for (int ks = 0; ks < 4; ks++) {
            uint32_t a[4][4];
#pragma unroll
            for (int mt = 0; mt < 4; mt++)
                ldm_x4(a[mt], sa + sw128((uint32_t)(wm * 64 + mt * 16 + a_lrow) * 128
                                          + ks * 32 + a_lcol));
#pragma unroll
            for (int ntp = 0; ntp < 4; ntp++) {
                uint32_t b[4];   // b[0..1]: n-tile 2*ntp, b[2..3]: n-tile 2*ntp+1
                ldm_x4(b, sbB + sw128((uint32_t)(wn * 64 + ntp * 16 + b_lrow) * 128
                                       + ks * 32 + b_lcol));
#pragma unroll
                for (int mt = 0; mt < 4; mt++) {
                    mma_bf16(acc[mt][2 * ntp],     a[mt], b);
                    mma_bf16(acc[mt][2 * ntp + 1], a[mt], b + 2);
                }
            }
        }
        __syncthreads();
    }

    // Epilogue: accum -> padded smem tile -> coalesced (2*s - esq) stores
    float* tile = (float*)smem;
#pragma unroll
    for (int mt = 0; mt < 4; mt++) {
        const int r = wm * 64 + mt * 16 + (lane >> 2);
#pragma unroll
        for (int nt = 0; nt < 8; nt++) {
            const int cb = wn * 64 + nt * 8 + 2 * (lane & 3);
            tile[r * 129 + cb]           = acc[mt][nt][0];
            tile[r * 129 + cb + 1]       = acc[mt][nt][1];
            tile[(r + 8) * 129 + cb]     = acc[mt][nt][2];
            tile[(r + 8) * 129 + cb + 1] = acc[mt][nt][3];
        }
    }
    __syncthreads();

#pragma unroll
    for (int i = 0; i < 32; i++) {
        const int lin = tid + i * 128;           // 0..4095
        const int row = lin >> 5;
        const int c4 = (lin & 31) * 4;
        const float4 esq = *(const float4*)(g_esq + bn + c4);
        float4 v;
        v.x = 2.f * tile[row * 129 + c4 + 0] - esq.x;
        v.y = 2.f * tile[row * 129 + c4 + 1] - esq.y;
        v.z = 2.f * tile[row * 129 + c4 + 2] - esq.z;
        v.w = 2.f * tile[row * 129 + c4 + 3] - esq.w;
        *(float4*)(g_scores + (size_t)(bm + row) * KC + bn + c4) = v;
    }
}

// ---------------------------------------------------------------------------
// Kernel 3: per-row argmax (+ exact fp32 rescue) + softmax + class-prob bins
// (register-resident) + outputs. Lane l of every warp owns the same k-set,
// so bins live in 64 regs/thread; merged once via warp-serialized smem adds.
// ---------------------------------------------------------------------------
__global__ __launch_bounds__(128) void row_kernel(const float* __restrict__ x,
                                                  const float* __restrict__ embed,
                                                  float* __restrict__ out) {
    __shared__ float cb_s[KC];      // 8 KB block class-prob accumulator
    __shared__ int s_cnt[4];
    __shared__ int s_list[4][16];
    const int tid = threadIdx.x;
    const int warp = tid >> 5, lane = tid & 31;

    for (int i = tid; i < KC; i += 128) cb_s[i] = 0.f;
    __syncthreads();

    const int row0 = blockIdx.x * 32;

    float bins[64];
#pragma unroll
    for (int j = 0; j < 64; j++) bins[j] = 0.f;

    for (int it = 0; it < 8; it++) {
        const int row = row0 + warp * 8 + it;
        const float* S = g_scores + (size_t)row * KC;

        float v[64];
        float m = -CUDART_INF_F;
        int mi = 0;
#pragma unroll
        for (int j = 0; j < 16; j++) {
            const int kbase = j * 128 + lane * 4;
            float4 q = *(const float4*)(S + kbase);
            v[4 * j + 0] = q.x; v[4 * j + 1] = q.y;
            v[4 * j + 2] = q.z; v[4 * j + 3] = q.w;
            if (q.x > m) { m = q.x; mi = kbase; }
            if (q.y > m) { m = q.y; mi = kbase + 1; }
            if (q.z > m) { m = q.z; mi = kbase + 2; }
            if (q.w > m) { m = q.w; mi = kbase + 3; }
        }
#pragma unroll
        for (int off = 16; off > 0; off >>= 1) {
            float om = __shfl_xor_sync(0xffffffffu, m, off);
            int oi = __shfl_xor_sync(0xffffffffu, mi, off);
            if (om > m || (om == m && oi < mi)) { m = om; mi = oi; }
        }

        // Candidate detection for exact rescue (before v[] is overwritten).
        const float thr = m - RESCUE_THR;
        int cnt = 0;
#pragma unroll
        for (int j = 0; j < 64; j++) cnt += (v[j] > thr) ? 1 : 0;
#pragma unroll
        for (int off = 16; off > 0; off >>= 1)
            cnt += __shfl_xor_sync(0xffffffffu, cnt, off);

        if (cnt > 1) {
            if (lane == 0) s_cnt[warp] = 0;
            __syncwarp();
#pragma unroll
            for (int j = 0; j < 64; j++) {
                if (v[j] > thr) {
                    int pos = atomicAdd(&s_cnt[warp], 1);
                    if (pos < 16)
                        s_list[warp][pos] = (j >> 2) * 128 + lane * 4 + (j & 3);
                }
            }
            __syncwarp();
            const int nc = min(s_cnt[warp], 16);
            const float4 xa = *(const float4*)(x + (size_t)row * D + lane * 4);
            float bv = -CUDART_INF_F; int bi = 0x7fffffff;
            for (int t = 0; t < nc; t++) {
                const int cidx = s_list[warp][t];
                const float4 ea = *(const float4*)(embed + (size_t)cidx * D + lane * 4);
                float d = xa.x * ea.x + xa.y * ea.y + xa.z * ea.z + xa.w * ea.w;
#pragma unroll
                for (int off = 16; off > 0; off >>= 1)
                    d += __shfl_xor_sync(0xffffffffu, d, off);
                const float sc = 2.f * d - g_esq[cidx];
                if (sc > bv || (sc == bv && cidx < bi)) { bv = sc; bi = cidx; }
            }
            mi = bi;
        }

        // softmax (approx scores — fine for the loss)
        float s = 0.f;
#pragma unroll
        for (int j = 0; j < 64; j++) {
            float e = __expf((v[j] - m) * TEMP_INV);
            v[j] = e;
            s += e;
        }
#pragma unroll
        for (int off = 16; off > 0; off >>= 1)
            s += __shfl_xor_sync(0xffffffffu, s, off);
        const float inv = 1.f / s;

#pragma unroll
        for (int j = 0; j < 64; j++) bins[j] = fmaf(v[j], inv, bins[j]);

        float4 q = *(const float4*)(embed + (size_t)mi * D + lane * 4);
        *(float4*)(out + (size_t)row * D + lane * 4) = q;
        if (lane == 0) out[(size_t)NP * D + row] = (float)mi;
    }

    // Deterministic cross-warp bin merge (warp-serialized smem adds)
    __syncthreads();
    for (int w = 0; w < 4; w++) {
        if (warp == w) {
#pragma unroll
            for (int j = 0; j < 16; j++) {
#pragma unroll
                for (int q = 0; q < 4; q++) {
                    const int k = j * 128 + lane * 4 + q;
                    cb_s[k] += bins[4 * j + q];
                }
            }
        }
        __syncthreads();
    }
    for (int i = tid; i < KC; i += 128)
        g_part[(size_t)blockIdx.x * KC + i] = cb_s[i];
}

// ---------------------------------------------------------------------------
// Kernel 4a/4b: two-stage deterministic reduce of partials
// ---------------------------------------------------------------------------
__global__ __launch_bounds__(256) void reduce1_kernel() {
    const int k = blockIdx.x * 256 + threadIdx.x;
    const int b0 = blockIdx.y * 64;
    float s0 = 0.f, s1 = 0.f, s2 = 0.f, s3 = 0.f;
    for (int b = 0; b < 64; b += 4) {
        s0 += g_part[(size_t)(b0 + b + 0) * KC + k];
        s1 += g_part[(size_t)(b0 + b + 1) * KC + k];
        s2 += g_part[(size_t)(b0 + b + 2) * KC + k];
        s3 += g_part[(size_t)(b0 + b + 3) * KC + k];
    }
    g_part2[blockIdx.y * KC + k] = (s0 + s1) + (s2 + s3);
}

__global__ __launch_bounds__(256) void reduce2_kernel() {
    const int k = blockIdx.x * 256 + threadIdx.x;
    float s = 0.f;
#pragma unroll
    for (int b = 0; b < 16; b++) s += g_part2[b * KC + k];
    g_acc[k] = s;
}

// ---------------------------------------------------------------------------
// Kernel 5: diversity loss
// ---------------------------------------------------------------------------
__global__ __launch_bounds__(256) void loss_kernel(float* __restrict__ out) {
    __shared__ float red[8];
    const int tid = threadIdx.x;
    float t = 0.f;
    for (int k = tid; k < KC; k += 256) {
        float p = g_acc[k] * (1.0f / (float)NP);
        t += p * logf(p + LEPS);
    }
#pragma unroll
    for (int off = 16; off > 0; off >>= 1)
        t += __shfl_xor_sync(0xffffffffu, t, off);
    if ((tid & 31) == 0) red[tid >> 5] = t;
    __syncthreads();
    if (tid < 8) {
        t = red[tid];
#pragma unroll
        for (int off = 4; off > 0; off >>= 1)
            t += __shfl_xor_sync(0x000000ffu, t, off);
        if (tid == 0) out[(size_t)NP * D + NP] = t;
    }
}

// ---------------------------------------------------------------------------
extern "C" void kernel_launch(void* const* d_in, const int* in_sizes, int n_in,
                              void* d_out, int out_size) {
    const float* x = (const float*)d_in[0];
    const float* e = (const float*)d_in[1];
    float* out = (float*)d_out;

    cudaFuncSetAttribute(gemm_kernel, cudaFuncAttributeMaxDynamicSharedMemorySize, GEMM_SMEM);

    split_kernel<<<((NP + KC) * D + 255) / 256, 256>>>(x, e);
    prep_kernel<<<(KC + 255) / 256, 256>>>(e);
    gemm_kernel<<<dim3(KC / 128, NP / 128), 128, GEMM_SMEM>>>();
    row_kernel<<<NP / 32, 128>>>(x, e, out);
    reduce1_kernel<<<dim3(KC / 256, 16), 256>>>();
    reduce2_kernel<<<KC / 256, 256>>>();
    loss_kernel<<<1, 256>>>(out);
}

// round 7
// speedup vs baseline: 1.3055x; 1.3055x over previous
#include <cuda_runtime.h>
#include <cuda_bf16.h>
#include <math_constants.h>
#include <cstdint>

// Problem dims (fixed by setup_inputs)
constexpr int NP = 32768;   // 8*4096 points
constexpr int KC = 2048;    // codebook size
constexpr int D  = 128;     // dim
constexpr float TEMP_INV = 1.0f / 0.9f;
constexpr float LEPS = 1e-6f;
constexpr float RESCUE_THR = 1e-2f;   // approx-score margin for exact rescoring

// Scratch (__device__ globals; no allocation allowed)
__device__ float g_scores[(size_t)NP * KC];            // 256 MB score matrix
__device__ float g_esq[KC];                            // ||e_k||^2
__device__ __nv_bfloat16 g_Xs[(size_t)NP * 256];       // 2-way bf16 split of x
__device__ __nv_bfloat16 g_Es[(size_t)KC * 256];       // 2-way bf16 split of embed
__device__ float g_part[(size_t)(NP / 32) * KC];       // per-block class-prob partials
__device__ float g_part2[16 * KC];                     // stage-1 reduced partials
__device__ float g_acc[KC];                            // class sums

// ---------------------------------------------------------------------------
__device__ __forceinline__ uint32_t smem_u32(const void* p) {
    uint32_t a;
    asm("{ .reg .u64 t; cvta.to.shared.u64 t, %1; cvt.u32.u64 %0, t; }" : "=r"(a) : "l"(p));
    return a;
}
__device__ __forceinline__ uint32_t sw128(uint32_t off) { return off ^ ((off >> 3) & 0x70); }

__device__ __forceinline__ void cp_async16(uint32_t saddr, const void* gaddr) {
    asm volatile("cp.async.cg.shared.global [%0], [%1], 16;" :: "r"(saddr), "l"(gaddr));
}
#define CP_COMMIT() asm volatile("cp.async.commit_group;" ::: "memory")
#define CP_WAIT(n)  asm volatile("cp.async.wait_group %0;" :: "n"(n) : "memory")

__device__ __forceinline__ void ldm_x4(uint32_t* a, uint32_t addr) {
    asm volatile("ldmatrix.sync.aligned.m8n8.x4.shared.b16 {%0,%1,%2,%3}, [%4];"
                 : "=r"(a[0]), "=r"(a[1]), "=r"(a[2]), "=r"(a[3]) : "r"(addr));
}
__device__ __forceinline__ void mma_bf16(float* c, const uint32_t* a, const uint32_t* b) {
    asm volatile("mma.sync.aligned.m16n8k16.row.col.f32.bf16.bf16.f32 "
                 "{%0,%1,%2,%3}, {%4,%5,%6,%7}, {%8,%9}, {%0,%1,%2,%3};"
                 : "+f"(c[0]), "+f"(c[1]), "+f"(c[2]), "+f"(c[3])
                 : "r"(a[0]), "r"(a[1]), "r"(a[2]), "r"(a[3]), "r"(b[0]), "r"(b[1]));
}

// ---------------------------------------------------------------------------
// Kernel 0: 2-way bf16 split of x and embed
// ---------------------------------------------------------------------------
__global__ __launch_bounds__(256) void split_kernel(const float* __restrict__ x,
                                                    const float* __restrict__ e) {
    int i = blockIdx.x * 256 + threadIdx.x;
    float v; __nv_bfloat16* dst; int c;
    if (i < NP * D) {
        v = x[i]; c = i & (D - 1);
        dst = g_Xs + (size_t)(i >> 7) * 256;
    } else {
        int j = i - NP * D;
        if (j >= KC * D) return;
        v = e[j]; c = j & (D - 1);
        dst = g_Es + (size_t)(j >> 7) * 256;
    }
    __nv_bfloat16 b0 = __float2bfloat16(v);
    float r1 = v - __bfloat162float(b0);
    __nv_bfloat16 b1 = __float2bfloat16(r1);
    dst[c] = b0; dst[128 + c] = b1;
}

// ---------------------------------------------------------------------------
// Kernel 1: e_sq
// ---------------------------------------------------------------------------
__global__ void prep_kernel(const float* __restrict__ embed) {
    int k = blockIdx.x * blockDim.x + threadIdx.x;
    if (k < KC) {
        const float4* e = (const float4*)(embed + (size_t)k * D);
        float s = 0.f;
#pragma unroll
        for (int i = 0; i < D / 4; i++) {
            float4 v = e[i];
            s += v.x * v.x + v.y * v.y + v.z * v.z + v.w * v.w;
        }
        g_esq[k] = s;
    }
}

// ---------------------------------------------------------------------------
// Kernel 2: mma.sync bf16 GEMM  S = 2*(X*E^T via 3 split-products) - e_sq
// Block 256 thr (8 warps), tile M128 x N128, warp tile 32x64.
// 6 K-chunks of 64 (virtual K=384), 3-stage cp.async, 1 barrier per chunk.
// B n-tiles paired into x4 ldmatrix.
// ---------------------------------------------------------------------------
constexpr int STG_SZ = 128 * 128;                 // 16 KB per operand stage
constexpr int GEMM_SMEM = 3 * 2 * STG_SZ;         // 98304 B (>= 66048 epilogue tile)

__constant__ int c_PA[3] = {0, 0, 1};
__constant__ int c_PB[3] = {0, 1, 0};

__global__ __launch_bounds__(256, 2) void gemm_kernel() {
    extern __shared__ char smem[];
    const uint32_t sb = smem_u32(smem);
    const int tid = threadIdx.x, wid = tid >> 5, lane = tid & 31;
    const int warp_m = wid & 3, warp_n = wid >> 2;
    const int bm = blockIdx.y * 128, bn = blockIdx.x * 128;

    float acc[2][8][4];
#pragma unroll
    for (int mt = 0; mt < 2; mt++)
#pragma unroll
        for (int nt = 0; nt < 8; nt++)
#pragma unroll
            for (int q = 0; q < 4; q++) acc[mt][nt][q] = 0.f;

    const int lr = tid >> 1;                 // rows 0..127 (2 threads/row)
    const int ls0 = (tid & 1) * 4;           // 16B segment base

    // A x4: 16 rows x 32B
    const int arow = warp_m * 32 + (lane & 7) + ((lane >> 3) & 1) * 8;
    const int acol = ((lane >> 4) & 1) * 16;
    // B x4 (two paired 8-row n-tiles): lanes 0-15 -> tile 2*ntp, 16-31 -> 2*ntp+1
    const int b_lrow = ((lane >> 4) & 1) * 8 + (lane & 7);
    const int b_lcol = ((lane >> 3) & 1) * 16;

    auto issue_chunk = [&](int c, int stage) {
        const int p = c >> 1, h = c & 1;
        const int aoff = c_PA[p] * 128 + h * 64;
        const int boff = c_PB[p] * 128 + h * 64;
        const uint32_t sa = sb + stage * 2 * STG_SZ;
        const uint32_t sbB = sa + STG_SZ;
        const __nv_bfloat16* ga = g_Xs + (size_t)(bm + lr) * 256 + aoff;
        const __nv_bfloat16* gb = g_Es + (size_t)(bn + lr) * 256 + boff;
#pragma unroll
        for (int s = 0; s < 4; s++) {
            cp_async16(sa + sw128((uint32_t)lr * 128 + (ls0 + s) * 16), ga + (ls0 + s) * 8);
            cp_async16(sbB + sw128((uint32_t)lr * 128 + (ls0 + s) * 16), gb + (ls0 + s) * 8);
        }
        CP_COMMIT();
    };

    issue_chunk(0, 0);
    issue_chunk(1, 1);

#pragma unroll 1
    for (int c = 0; c < 6; c++) {
        const int stage = c % 3;
        if (c < 5) { CP_WAIT(1); } else { CP_WAIT(0); }
        __syncthreads();   // chunk c visible to all; buffer (c+2)%3 free (computed at c-1)

        const uint32_t sa = sb + stage * 2 * STG_SZ;
        const uint32_t sbB = sa + STG_SZ;
#pragma unroll
        for (int ks = 0; ks < 4; ks++) {
            uint32_t a[2][4];
#pragma unroll
            for (int mt = 0; mt < 2; mt++)
                ldm_x4(a[mt], sa + sw128((uint32_t)(arow + mt * 16) * 128 + ks * 32 + acol));
#pragma unroll
            for (int ntp = 0; ntp < 4; ntp++) {
                uint32_t b[4];
                ldm_x4(b, sbB + sw128((uint32_t)(warp_n * 64 + ntp * 16 + b_lrow) * 128
                                       + ks * 32 + b_lcol));
                mma_bf16(acc[0][2 * ntp],     a[0], b);
                mma_bf16(acc[1][2 * ntp],     a[1], b);
                mma_bf16(acc[0][2 * ntp + 1], a[0], b + 2);
                mma_bf16(acc[1][2 * ntp + 1], a[1], b + 2);
            }
        }
        if (c <= 3) issue_chunk(c + 2, (c + 2) % 3);
    }
    __syncthreads();   // all compute done before smem reuse by epilogue

    // Epilogue: accum -> padded smem tile -> coalesced (2*s - esq) stores
    float* tile = (float*)smem;
#pragma unroll
    for (int mt = 0; mt < 2; mt++) {
        const int r = warp_m * 32 + mt * 16 + (lane >> 2);
#pragma unroll
        for (int nt = 0; nt < 8; nt++) {
            const int cb = warp_n * 64 + nt * 8 + 2 * (lane & 3);
            tile[r * 129 + cb]           = acc[mt][nt][0];
            tile[r * 129 + cb + 1]       = acc[mt][nt][1];
            tile[(r + 8) * 129 + cb]     = acc[mt][nt][2];
            tile[(r + 8) * 129 + cb + 1] = acc[mt][nt][3];
        }
    }
    __syncthreads();

#pragma unroll
    for (int i = 0; i < 16; i++) {
        const int lin = tid + i * 256;           // 0..4095
        const int row = lin >> 5;
        const int c4 = (lin & 31) * 4;
        const float4 esq = *(const float4*)(g_esq + bn + c4);
        float4 v;
        v.x = 2.f * tile[row * 129 + c4 + 0] - esq.x;
        v.y = 2.f * tile[row * 129 + c4 + 1] - esq.y;
        v.z = 2.f * tile[row * 129 + c4 + 2] - esq.z;
        v.w = 2.f * tile[row * 129 + c4 + 3] - esq.w;
        *(float4*)(g_scores + (size_t)(bm + row) * KC + bn + c4) = v;
    }
}

// ---------------------------------------------------------------------------
// Kernel 3: per-row argmax (+ exact fp32 rescue) + softmax + class-prob
// partials + outputs. (R5 version — 128 thr, smem accumulators, 72 us.)
// ---------------------------------------------------------------------------
__global__ __launch_bounds__(128) void row_kernel(const float* __restrict__ x,
                                                  const float* __restrict__ embed,
                                                  float* __restrict__ out) {
    __shared__ float cp[4][KC];
    __shared__ int s_cnt[4];
    __shared__ int s_list[4][16];
    const int tid = threadIdx.x;
    const int warp = tid >> 5, lane = tid & 31;

    for (int i = tid; i < 4 * KC; i += 128) (&cp[0][0])[i] = 0.f;
    __syncthreads();

    const int row0 = blockIdx.x * 32;
    float* cpw = cp[warp];

    for (int it = 0; it < 8; it++) {
        const int row = row0 + warp * 8 + it;
        const float* S = g_scores + (size_t)row * KC;

        float v[64];
        float m = -CUDART_INF_F;
        int mi = 0;
#pragma unroll
        for (int j = 0; j < 16; j++) {
            const int kbase = j * 128 + lane * 4;
            float4 q = *(const float4*)(S + kbase);
            v[4 * j + 0] = q.x; v[4 * j + 1] = q.y;
            v[4 * j + 2] = q.z; v[4 * j + 3] = q.w;
            if (q.x > m) { m = q.x; mi = kbase; }
            if (q.y > m) { m = q.y; mi = kbase + 1; }
            if (q.z > m) { m = q.z; mi = kbase + 2; }
            if (q.w > m) { m = q.w; mi = kbase + 3; }
        }
#pragma unroll
        for (int off = 16; off > 0; off >>= 1) {
            float om = __shfl_xor_sync(0xffffffffu, m, off);
            int oi = __shfl_xor_sync(0xffffffffu, mi, off);
            if (om > m || (om == m && oi < mi)) { m = om; mi = oi; }
        }

        // Candidate detection for exact rescue (before v[] is overwritten).
        const float thr = m - RESCUE_THR;
        int cnt = 0;
#pragma unroll
        for (int j = 0; j < 64; j++) cnt += (v[j] > thr) ? 1 : 0;
#pragma unroll
        for (int off = 16; off > 0; off >>= 1)
            cnt += __shfl_xor_sync(0xffffffffu, cnt, off);

        if (cnt > 1) {
            if (lane == 0) s_cnt[warp] = 0;
            __syncwarp();
#pragma unroll
            for (int j = 0; j < 64; j++) {
                if (v[j] > thr) {
                    int pos = atomicAdd(&s_cnt[warp], 1);
                    if (pos < 16)
                        s_list[warp][pos] = (j >> 2) * 128 + lane * 4 + (j & 3);
                }
            }
            __syncwarp();
            const int nc = min(s_cnt[warp], 16);
            const float4 xa = *(const float4*)(x + (size_t)row * D + lane * 4);
            float bv = -CUDART_INF_F; int bi = 0x7fffffff;
            for (int t = 0; t < nc; t++) {
                const int cidx = s_list[warp][t];
                const float4 ea = *(const float4*)(embed + (size_t)cidx * D + lane * 4);
                float d = xa.x * ea.x + xa.y * ea.y + xa.z * ea.z + xa.w * ea.w;
#pragma unroll
                for (int off = 16; off > 0; off >>= 1)
                    d += __shfl_xor_sync(0xffffffffu, d, off);
                const float sc = 2.f * d - g_esq[cidx];
                if (sc > bv || (sc == bv && cidx < bi)) { bv = sc; bi = cidx; }
            }
            mi = bi;
        }

        // softmax (approx scores — fine for the loss)
        float s = 0.f;
#pragma unroll
        for (int j = 0; j < 64; j++) {
            float e = __expf((v[j] - m) * TEMP_INV);
            v[j] = e;
            s += e;
        }
#pragma unroll
        for (int off = 16; off > 0; off >>= 1)
            s += __shfl_xor_sync(0xffffffffu, s, off);
        const float inv = 1.f / s;

#pragma unroll
        for (int j = 0; j < 16; j++) {
            float4* p = (float4*)(cpw + j * 128 + lane * 4);
            float4 c = *p;
            c.x += v[4 * j + 0] * inv; c.y += v[4 * j + 1] * inv;
            c.z += v[4 * j + 2] * inv; c.w += v[4 * j + 3] * inv;
            *p = c;
        }

        float4 q = *(const float4*)(embed + (size_t)mi * D + lane * 4);
        *(float4*)(out + (size_t)row * D + lane * 4) = q;
        if (lane == 0) out[(size_t)NP * D + row] = (float)mi;
    }

    __syncthreads();
    for (int i = tid; i < KC; i += 128)
        g_part[(size_t)blockIdx.x * KC + i] =
            cp[0][i] + cp[1][i] + cp[2][i] + cp[3][i];
}

// ---------------------------------------------------------------------------
// Kernel 4a/4b: two-stage deterministic reduce of partials
// ---------------------------------------------------------------------------
__global__ __launch_bounds__(256) void reduce1_kernel() {
    const int k = blockIdx.x * 256 + threadIdx.x;
    const int b0 = blockIdx.y * 64;
    float s0 = 0.f, s1 = 0.f, s2 = 0.f, s3 = 0.f;
    for (int b = 0; b < 64; b += 4) {
        s0 += g_part[(size_t)(b0 + b + 0) * KC + k];
        s1 += g_part[(size_t)(b0 + b + 1) * KC + k];
        s2 += g_part[(size_t)(b0 + b + 2) * KC + k];
        s3 += g_part[(size_t)(b0 + b + 3) * KC + k];
    }
    g_part2[blockIdx.y * KC + k] = (s0 + s1) + (s2 + s3);
}

__global__ __launch_bounds__(256) void reduce2_kernel() {
    const int k = blockIdx.x * 256 + threadIdx.x;
    float s = 0.f;
#pragma unroll
    for (int b = 0; b < 16; b++) s += g_part2[b * KC + k];
    g_acc[k] = s;
}

// ---------------------------------------------------------------------------
// Kernel 5: diversity loss
// ---------------------------------------------------------------------------
__global__ __launch_bounds__(256) void loss_kernel(float* __restrict__ out) {
    __shared__ float red[8];
    const int tid = threadIdx.x;
    float t = 0.f;
    for (int k = tid; k < KC; k += 256) {
        float p = g_acc[k] * (1.0f / (float)NP);
        t += p * logf(p + LEPS);
    }
#pragma unroll
    for (int off = 16; off > 0; off >>= 1)
        t += __shfl_xor_sync(0xffffffffu, t, off);
    if ((tid & 31) == 0) red[tid >> 5] = t;
    __syncthreads();
    if (tid < 8) {
        t = red[tid];
#pragma unroll
        for (int off = 4; off > 0; off >>= 1)
            t += __shfl_xor_sync(0x000000ffu, t, off);
        if (tid == 0) out[(size_t)NP * D + NP] = t;
    }
}

// ---------------------------------------------------------------------------
extern "C" void kernel_launch(void* const* d_in, const int* in_sizes, int n_in,
                              void* d_out, int out_size) {
    const float* x = (const float*)d_in[0];
    const float* e = (const float*)d_in[1];
    float* out = (float*)d_out;

    cudaFuncSetAttribute(gemm_kernel, cudaFuncAttributeMaxDynamicSharedMemorySize, GEMM_SMEM);

    split_kernel<<<((NP + KC) * D + 255) / 256, 256>>>(x, e);
    prep_kernel<<<(KC + 255) / 256, 256>>>(e);
    gemm_kernel<<<dim3(KC / 128, NP / 128), 256, GEMM_SMEM>>>();
    row_kernel<<<NP / 32, 128>>>(x, e, out);
    reduce1_kernel<<<dim3(KC / 256, 16), 256>>>();
    reduce2_kernel<<<KC / 256, 256>>>();
    loss_kernel<<<1, 256>>>(out);
}

// round 9
// speedup vs baseline: 1.5267x; 1.1695x over previous
#include <cuda_runtime.h>
#include <cuda_bf16.h>
#include <math_constants.h>
#include <cstdint>

// Problem dims (fixed by setup_inputs)
constexpr int NP = 32768;   // 8*4096 points
constexpr int KC = 2048;    // codebook size
constexpr int D  = 128;     // dim
constexpr float TEMP_INV = 1.0f / 0.9f;
constexpr float LEPS = 1e-6f;
constexpr float RESCUE_THR = 0.25f;   // 2-product score error sigma ~0.025 -> 10 sigma

// Scratch (__device__ globals; no allocation allowed)
__device__ float g_scores[(size_t)NP * KC];            // 256 MB score matrix
__device__ float g_esq[KC];                            // ||e_k||^2
__device__ __nv_bfloat16 g_Xs[(size_t)NP * 128];       // bf16(x) (8 MB)
__device__ __nv_bfloat16 g_Es[(size_t)KC * 256];       // 2-way bf16 split of embed
__device__ float g_part[(size_t)(NP / 32) * KC];       // per-block class-prob partials
__device__ float g_part2[16 * KC];                     // stage-1 reduced partials
__device__ float g_acc[KC];                            // class sums

// ---------------------------------------------------------------------------
__device__ __forceinline__ uint32_t smem_u32(const void* p) {
    uint32_t a;
    asm("{ .reg .u64 t; cvta.to.shared.u64 t, %1; cvt.u32.u64 %0, t; }" : "=r"(a) : "l"(p));
    return a;
}
__device__ __forceinline__ uint32_t sw128(uint32_t off) { return off ^ ((off >> 3) & 0x70); }

__device__ __forceinline__ void cp_async16(uint32_t saddr, const void* gaddr) {
    asm volatile("cp.async.cg.shared.global [%0], [%1], 16;" :: "r"(saddr), "l"(gaddr));
}
#define CP_COMMIT() asm volatile("cp.async.commit_group;" ::: "memory")
#define CP_WAIT(n)  asm volatile("cp.async.wait_group %0;" :: "n"(n) : "memory")

__device__ __forceinline__ void ldm_x4(uint32_t* a, uint32_t addr) {
    asm volatile("ldmatrix.sync.aligned.m8n8.x4.shared.b16 {%0,%1,%2,%3}, [%4];"
                 : "=r"(a[0]), "=r"(a[1]), "=r"(a[2]), "=r"(a[3]) : "r"(addr));
}
__device__ __forceinline__ void mma_bf16(float* c, const uint32_t* a, const uint32_t* b) {
    asm volatile("mma.sync.aligned.m16n8k16.row.col.f32.bf16.bf16.f32 "
                 "{%0,%1,%2,%3}, {%4,%5,%6,%7}, {%8,%9}, {%0,%1,%2,%3};"
                 : "+f"(c[0]), "+f"(c[1]), "+f"(c[2]), "+f"(c[3])
                 : "r"(a[0]), "r"(a[1]), "r"(a[2]), "r"(a[3]), "r"(b[0]), "r"(b[1]));
}

// ---------------------------------------------------------------------------
// Kernel 0: bf16 conversion of x; 2-way bf16 split of embed
// ---------------------------------------------------------------------------
__global__ __launch_bounds__(256) void split_kernel(const float* __restrict__ x,
                                                    const float* __restrict__ e) {
    int i = blockIdx.x * 256 + threadIdx.x;
    if (i < NP * D) {
        g_Xs[i] = __float2bfloat16(x[i]);
    } else {
        int j = i - NP * D;
        if (j >= KC * D) return;
        float v = e[j];
        int c = j & (D - 1);
        __nv_bfloat16* dst = g_Es + (size_t)(j >> 7) * 256;
        __nv_bfloat16 b0 = __float2bfloat16(v);
        float r1 = v - __bfloat162float(b0);
        __nv_bfloat16 b1 = __float2bfloat16(r1);
        dst[c] = b0; dst[128 + c] = b1;
    }
}

// ---------------------------------------------------------------------------
// Kernel 1: e_sq
// ---------------------------------------------------------------------------
__global__ void prep_kernel(const float* __restrict__ embed) {
    int k = blockIdx.x * blockDim.x + threadIdx.x;
    if (k < KC) {
        const float4* e = (const float4*)(embed + (size_t)k * D);
        float s = 0.f;
#pragma unroll
        for (int i = 0; i < D / 4; i++) {
            float4 v = e[i];
            s += v.x * v.x + v.y * v.y + v.z * v.z + v.w * v.w;
        }
        g_esq[k] = s;
    }
}

// ---------------------------------------------------------------------------
// Kernel 2: mma.sync bf16 GEMM  S = 2*(x0*e0 + x0*e1) - e_sq
// Block 256 thr (8 warps), tile M128 x N128, warp tile 32x64.
// 4 K-chunks of 64 (virtual K=256), 3-stage cp.async, 1 barrier per chunk.
// ---------------------------------------------------------------------------
constexpr int STG_SZ = 128 * 128;                 // 16 KB per operand stage
constexpr int GEMM_SMEM = 3 * 2 * STG_SZ;         // 98304 B (>= 66048 epilogue tile)

__global__ __launch_bounds__(256, 2) void gemm_kernel() {
    extern __shared__ char smem[];
    const uint32_t sb = smem_u32(smem);
    const int tid = threadIdx.x, wid = tid >> 5, lane = tid & 31;
    const int warp_m = wid & 3, warp_n = wid >> 2;
    const int bm = blockIdx.y * 128, bn = blockIdx.x * 128;

    float acc[2][8][4];
#pragma unroll
    for (int mt = 0; mt < 2; mt++)
#pragma unroll
        for (int nt = 0; nt < 8; nt++)
#pragma unroll
            for (int q = 0; q < 4; q++) acc[mt][nt][q] = 0.f;

    const int lr = tid >> 1;                 // rows 0..127 (2 threads/row)
    const int ls0 = (tid & 1) * 4;           // 16B segment base

    // A x4: 16 rows x 32B
    const int arow = warp_m * 32 + (lane & 7) + ((lane >> 3) & 1) * 8;
    const int acol = ((lane >> 4) & 1) * 16;
    // B x4 (two paired 8-row n-tiles)
    const int b_lrow = ((lane >> 4) & 1) * 8 + (lane & 7);
    const int b_lcol = ((lane >> 3) & 1) * 16;

    // chunk c: p = c>>1 selects e0/e1, h = c&1 selects 64-dim half.
    auto issue_chunk = [&](int c, int stage) {
        const int p = c >> 1, h = c & 1;
        const uint32_t sa = sb + stage * 2 * STG_SZ;
        const uint32_t sbB = sa + STG_SZ;
        const __nv_bfloat16* ga = g_Xs + (size_t)(bm + lr) * 128 + h * 64;
        const __nv_bfloat16* gb = g_Es + (size_t)(bn + lr) * 256 + p * 128 + h * 64;
#pragma unroll
        for (int s = 0; s < 4; s++) {
            cp_async16(sa + sw128((uint32_t)lr * 128 + (ls0 + s) * 16), ga + (ls0 + s) * 8);
            cp_async16(sbB + sw128((uint32_t)lr * 128 + (ls0 + s) * 16), gb + (ls0 + s) * 8);
        }
        CP_COMMIT();
    };

    issue_chunk(0, 0);
    issue_chunk(1, 1);

#pragma unroll 1
    for (int c = 0; c < 4; c++) {
        const int stage = c % 3;
        if (c < 3) { CP_WAIT(1); } else { CP_WAIT(0); }
        __syncthreads();

        const uint32_t sa = sb + stage * 2 * STG_SZ;
        const uint32_t sbB = sa + STG_SZ;
#pragma unroll
        for (int ks = 0; ks < 4; ks++) {
            uint32_t a[2][4];
#pragma unroll
            for (int mt = 0; mt < 2; mt++)
                ldm_x4(a[mt], sa + sw128((uint32_t)(arow + mt * 16) * 128 + ks * 32 + acol));
#pragma unroll
            for (int ntp = 0; ntp < 4; ntp++) {
                uint32_t b[4];
                ldm_x4(b, sbB + sw128((uint32_t)(warp_n * 64 + ntp * 16 + b_lrow) * 128
                                       + ks * 32 + b_lcol));
                mma_bf16(acc[0][2 * ntp],     a[0], b);
                mma_bf16(acc[1][2 * ntp],     a[1], b);
                mma_bf16(acc[0][2 * ntp + 1], a[0], b + 2);
                mma_bf16(acc[1][2 * ntp + 1], a[1], b + 2);
            }
        }
        if (c <= 1) issue_chunk(c + 2, (c + 2) % 3);
    }
    __syncthreads();

    // Epilogue: accum -> padded smem tile -> coalesced (2*s - esq) stores
    float* tile = (float*)smem;
#pragma unroll
    for (int mt = 0; mt < 2; mt++) {
        const int r = warp_m * 32 + mt * 16 + (lane >> 2);
#pragma unroll
        for (int nt = 0; nt < 8; nt++) {
            const int cb = warp_n * 64 + nt * 8 + 2 * (lane & 3);
            tile[r * 129 + cb]           = acc[mt][nt][0];
            tile[r * 129 + cb + 1]       = acc[mt][nt][1];
            tile[(r + 8) * 129 + cb]     = acc[mt][nt][2];
            tile[(r + 8) * 129 + cb + 1] = acc[mt][nt][3];
        }
    }
    __syncthreads();

#pragma unroll
    for (int i = 0; i < 16; i++) {
        const int lin = tid + i * 256;           // 0..4095
        const int row = lin >> 5;
        const int c4 = (lin & 31) * 4;
        const float4 esq = *(const float4*)(g_esq + bn + c4);
        float4 v;
        v.x = 2.f * tile[row * 129 + c4 + 0] - esq.x;
        v.y = 2.f * tile[row * 129 + c4 + 1] - esq.y;
        v.z = 2.f * tile[row * 129 + c4 + 2] - esq.z;
        v.w = 2.f * tile[row * 129 + c4 + 3] - esq.w;
        *(float4*)(g_scores + (size_t)(bm + row) * KC + bn + c4) = v;
    }
}

// ---------------------------------------------------------------------------
// Kernel 3: per-row argmax (+ exact fp32 rescue) + softmax + class-prob
// partials + outputs.
// ---------------------------------------------------------------------------
__global__ __launch_bounds__(128) void row_kernel(const float* __restrict__ x,
                                                  const float* __restrict__ embed,
                                                  float* __restrict__ out) {
    __shared__ float cp[4][KC];
    __shared__ int s_cnt[4];
    __shared__ int s_list[4][32];
    const int tid = threadIdx.x;
    const int warp = tid >> 5, lane = tid & 31;

    for (int i = tid; i < 4 * KC; i += 128) (&cp[0][0])[i] = 0.f;
    __syncthreads();

    const int row0 = blockIdx.x * 32;
    float* cpw = cp[warp];

    for (int it = 0; it < 8; it++) {
        const int row = row0 + warp * 8 + it;
        const float* S = g_scores + (size_t)row * KC;

        float v[64];
        float m = -CUDART_INF_F;
        int mi = 0;
#pragma unroll
        for (int j = 0; j < 16; j++) {
            const int kbase = j * 128 + lane * 4;
            float4 q = *(const float4*)(S + kbase);
            v[4 * j + 0] = q.x; v[4 * j + 1] = q.y;
            v[4 * j + 2] = q.z; v[4 * j + 3] = q.w;
            if (q.x > m) { m = q.x; mi = kbase; }
            if (q.y > m) { m = q.y; mi = kbase + 1; }
            if (q.z > m) { m = q.z; mi = kbase + 2; }
            if (q.w > m) { m = q.w; mi = kbase + 3; }
        }
#pragma unroll
        for (int off = 16; off > 0; off >>= 1) {
            float om = __shfl_xor_sync(0xffffffffu, m, off);
            int oi = __shfl_xor_sync(0xffffffffu, mi, off);
            if (om > m || (om == m && oi < mi)) { m = om; mi = oi; }
        }

        // Candidate detection for exact rescue (before v[] is overwritten).
        const float thr = m - RESCUE_THR;
        int cnt = 0;
#pragma unroll
        for (int j = 0; j < 64; j++) cnt += (v[j] > thr) ? 1 : 0;
#pragma unroll
        for (int off = 16; off > 0; off >>= 1)
            cnt += __shfl_xor_sync(0xffffffffu, cnt, off);

        if (cnt > 1) {
            if (lane == 0) s_cnt[warp] = 0;
            __syncwarp();
#pragma unroll
            for (int j = 0; j < 64; j++) {
                if (v[j] > thr) {
                    int pos = atomicAdd(&s_cnt[warp], 1);
                    if (pos < 32)
                        s_list[warp][pos] = (j >> 2) * 128 + lane * 4 + (j & 3);
                }
            }
            __syncwarp();
            const int nc = min(s_cnt[warp], 32);
            const float4 xa = *(const float4*)(x + (size_t)row * D + lane * 4);
            float bv = -CUDART_INF_F; int bi = 0x7fffffff;
            for (int t = 0; t < nc; t++) {
                const int cidx = s_list[warp][t];
                const float4 ea = *(const float4*)(embed + (size_t)cidx * D + lane * 4);
                float d = xa.x * ea.x + xa.y * ea.y + xa.z * ea.z + xa.w * ea.w;
#pragma unroll
                for (int off = 16; off > 0; off >>= 1)
                    d += __shfl_xor_sync(0xffffffffu, d, off);
                const float sc = 2.f * d - g_esq[cidx];
                if (sc > bv || (sc == bv && cidx < bi)) { bv = sc; bi = cidx; }
            }
            mi = bi;
        }

        // softmax (approx scores — fine for the loss)
        float s = 0.f;
#pragma unroll
        for (int j = 0; j < 64; j++) {
            float e = __expf((v[j] - m) * TEMP_INV);
            v[j] = e;
            s += e;
        }
#pragma unroll
        for (int off = 16; off > 0; off >>= 1)
            s += __shfl_xor_sync(0xffffffffu, s, off);
        const float inv = 1.f / s;

#pragma unroll
        for (int j = 0; j < 16; j++) {
            float4* p = (float4*)(cpw + j * 128 + lane * 4);
            float4 c = *p;
            c.x += v[4 * j + 0] * inv; c.y += v[4 * j + 1] * inv;
            c.z += v[4 * j + 2] * inv; c.w += v[4 * j + 3] * inv;
            *p = c;
        }

        float4 q = *(const float4*)(embed + (size_t)mi * D + lane * 4);
        *(float4*)(out + (size_t)row * D + lane * 4) = q;
        if (lane == 0) out[(size_t)NP * D + row] = (float)mi;
    }

    __syncthreads();
    for (int i = tid; i < KC; i += 128)
        g_part[(size_t)blockIdx.x * KC + i] =
            cp[0][i] + cp[1][i] + cp[2][i] + cp[3][i];
}

// ---------------------------------------------------------------------------
// Kernel 4a/4b: two-stage deterministic reduce of partials
// ---------------------------------------------------------------------------
__global__ __launch_bounds__(256) void reduce1_kernel() {
    const int k = blockIdx.x * 256 + threadIdx.x;
    const int b0 = blockIdx.y * 64;
    float s0 = 0.f, s1 = 0.f, s2 = 0.f, s3 = 0.f;
    for (int b = 0; b < 64; b += 4) {
        s0 += g_part[(size_t)(b0 + b + 0) * KC + k];
        s1 += g_part[(size_t)(b0 + b + 1) * KC + k];
        s2 += g_part[(size_t)(b0 + b + 2) * KC + k];
        s3 += g_part[(size_t)(b0 + b + 3) * KC + k];
    }
    g_part2[blockIdx.y * KC + k] = (s0 + s1) + (s2 + s3);
}

__global__ __launch_bounds__(256) void reduce2_kernel() {
    const int k = blockIdx.x * 256 + threadIdx.x;
    float s = 0.f;
#pragma unroll
    for (int b = 0; b < 16; b++) s += g_part2[b * KC + k];
    g_acc[k] = s;
}

// ---------------------------------------------------------------------------
// Kernel 5: diversity loss
// ---------------------------------------------------------------------------
__global__ __launch_bounds__(256) void loss_kernel(float* __restrict__ out) {
    __shared__ float red[8];
    const int tid = threadIdx.x;
    float t = 0.f;
    for (int k = tid; k < KC; k += 256) {
        float p = g_acc[k] * (1.0f / (float)NP);
        t += p * logf(p + LEPS);
    }
#pragma unroll
    for (int off = 16; off > 0; off >>= 1)
        t += __shfl_xor_sync(0xffffffffu, t, off);
    if ((tid & 31) == 0) red[tid >> 5] = t;
    __syncthreads();
    if (tid < 8) {
        t = red[tid];
#pragma unroll
        for (int off = 4; off > 0; off >>= 1)
            t += __shfl_xor_sync(0x000000ffu, t, off);
        if (tid == 0) out[(size_t)NP * D + NP] = t;
    }
}

// ---------------------------------------------------------------------------
extern "C" void kernel_launch(void* const* d_in, const int* in_sizes, int n_in,
                              void* d_out, int out_size) {
    const float* x = (const float*)d_in[0];
    const float* e = (const float*)d_in[1];
    float* out = (float*)d_out;

    cudaFuncSetAttribute(gemm_kernel, cudaFuncAttributeMaxDynamicSharedMemorySize, GEMM_SMEM);

    split_kernel<<<((NP + KC) * D + 255) / 256, 256>>>(x, e);
    prep_kernel<<<(KC + 255) / 256, 256>>>(e);
    gemm_kernel<<<dim3(KC / 128, NP / 128), 256, GEMM_SMEM>>>();
    row_kernel<<<NP / 32, 128>>>(x, e, out);
    reduce1_kernel<<<dim3(KC / 256, 16), 256>>>();
    reduce2_kernel<<<KC / 256, 256>>>();
    loss_kernel<<<1, 256>>>(out);
}

// round 10
// speedup vs baseline: 1.6239x; 1.0637x over previous
#include <cuda_runtime.h>
#include <cuda_bf16.h>
#include <cuda_fp16.h>
#include <math_constants.h>
#include <cstdint>

// Problem dims (fixed by setup_inputs)
constexpr int NP = 32768;   // 8*4096 points
constexpr int KC = 2048;    // codebook size
constexpr int D  = 128;     // dim
constexpr float TEMP_INV = 1.0f / 0.9f;
constexpr float LEPS = 1e-6f;
constexpr float RESCUE_THR = 0.5f;    // covers split (0.125) + fp16 quant (0.125) stack
constexpr float OFFS = 128.0f;        // recenters S ~ -128+-28 to ~0 for fp16 storage

// Scratch (__device__ globals; no allocation allowed)
__device__ __half g_scores16[(size_t)NP * KC];         // 128 MB score matrix (S + OFFS)
__device__ float g_esq[KC];                            // ||e_k||^2
__device__ __nv_bfloat16 g_Xs[(size_t)NP * 128];       // bf16(x) (8 MB)
__device__ __nv_bfloat16 g_Es[(size_t)KC * 256];       // 2-way bf16 split of embed
__device__ float g_part[(size_t)(NP / 32) * KC];       // per-block class-prob partials
__device__ float g_part2[16 * KC];                     // stage-1 reduced partials
__device__ float g_acc[KC];                            // class sums

// ---------------------------------------------------------------------------
__device__ __forceinline__ uint32_t smem_u32(const void* p) {
    uint32_t a;
    asm("{ .reg .u64 t; cvta.to.shared.u64 t, %1; cvt.u32.u64 %0, t; }" : "=r"(a) : "l"(p));
    return a;
}
__device__ __forceinline__ uint32_t sw128(uint32_t off) { return off ^ ((off >> 3) & 0x70); }

__device__ __forceinline__ void cp_async16(uint32_t saddr, const void* gaddr) {
    asm volatile("cp.async.cg.shared.global [%0], [%1], 16;" :: "r"(saddr), "l"(gaddr));
}
#define CP_COMMIT() asm volatile("cp.async.commit_group;" ::: "memory")
#define CP_WAIT(n)  asm volatile("cp.async.wait_group %0;" :: "n"(n) : "memory")

__device__ __forceinline__ void ldm_x4(uint32_t* a, uint32_t addr) {
    asm volatile("ldmatrix.sync.aligned.m8n8.x4.shared.b16 {%0,%1,%2,%3}, [%4];"
                 : "=r"(a[0]), "=r"(a[1]), "=r"(a[2]), "=r"(a[3]) : "r"(addr));
}
__device__ __forceinline__ void mma_bf16(float* c, const uint32_t* a, const uint32_t* b) {
    asm volatile("mma.sync.aligned.m16n8k16.row.col.f32.bf16.bf16.f32 "
                 "{%0,%1,%2,%3}, {%4,%5,%6,%7}, {%8,%9}, {%0,%1,%2,%3};"
                 : "+f"(c[0]), "+f"(c[1]), "+f"(c[2]), "+f"(c[3])
                 : "r"(a[0]), "r"(a[1]), "r"(a[2]), "r"(a[3]), "r"(b[0]), "r"(b[1]));
}

// ---------------------------------------------------------------------------
// Kernel 0: bf16 conversion of x; 2-way bf16 split of embed
// ---------------------------------------------------------------------------
__global__ __launch_bounds__(256) void split_kernel(const float* __restrict__ x,
                                                    const float* __restrict__ e) {
    int i = blockIdx.x * 256 + threadIdx.x;
    if (i < NP * D) {
        g_Xs[i] = __float2bfloat16(x[i]);
    } else {
        int j = i - NP * D;
        if (j >= KC * D) return;
        float v = e[j];
        int c = j & (D - 1);
        __nv_bfloat16* dst = g_Es + (size_t)(j >> 7) * 256;
        __nv_bfloat16 b0 = __float2bfloat16(v);
        float r1 = v - __bfloat162float(b0);
        __nv_bfloat16 b1 = __float2bfloat16(r1);
        dst[c] = b0; dst[128 + c] = b1;
    }
}

// ---------------------------------------------------------------------------
// Kernel 1: e_sq
// ---------------------------------------------------------------------------
__global__ void prep_kernel(const float* __restrict__ embed) {
    int k = blockIdx.x * blockDim.x + threadIdx.x;
    if (k < KC) {
        const float4* e = (const float4*)(embed + (size_t)k * D);
        float s = 0.f;
#pragma unroll
        for (int i = 0; i < D / 4; i++) {
            float4 v = e[i];
            s += v.x * v.x + v.y * v.y + v.z * v.z + v.w * v.w;
        }
        g_esq[k] = s;
    }
}

// ---------------------------------------------------------------------------
// Kernel 2: mma.sync bf16 GEMM  S16 = fp16(2*(x0*e0 + x0*e1) - e_sq + OFFS)
// Block 256 thr (8 warps), tile M128 x N128, warp tile 32x64.
// 4 K-chunks of 64 (virtual K=256), 3-stage cp.async, 1 barrier per chunk.
// ---------------------------------------------------------------------------
constexpr int STG_SZ = 128 * 128;                 // 16 KB per operand stage
constexpr int GEMM_SMEM = 3 * 2 * STG_SZ;         // 98304 B (>= 66048 epilogue tile)

__global__ __launch_bounds__(256, 2) void gemm_kernel() {
    extern __shared__ char smem[];
    const uint32_t sb = smem_u32(smem);
    const int tid = threadIdx.x, wid = tid >> 5, lane = tid & 31;
    const int warp_m = wid & 3, warp_n = wid >> 2;
    const int bm = blockIdx.y * 128, bn = blockIdx.x * 128;

    float acc[2][8][4];
#pragma unroll
    for (int mt = 0; mt < 2; mt++)
#pragma unroll
        for (int nt = 0; nt < 8; nt++)
#pragma unroll
            for (int q = 0; q < 4; q++) acc[mt][nt][q] = 0.f;

    const int lr = tid >> 1;                 // rows 0..127 (2 threads/row)
    const int ls0 = (tid & 1) * 4;           // 16B segment base

    // A x4: 16 rows x 32B
    const int arow = warp_m * 32 + (lane & 7) + ((lane >> 3) & 1) * 8;
    const int acol = ((lane >> 4) & 1) * 16;
    // B x4 (two paired 8-row n-tiles)
    const int b_lrow = ((lane >> 4) & 1) * 8 + (lane & 7);
    const int b_lcol = ((lane >> 3) & 1) * 16;

    // chunk c: p = c>>1 selects e0/e1, h = c&1 selects 64-dim half.
    auto issue_chunk = [&](int c, int stage) {
        const int p = c >> 1, h = c & 1;
        const uint32_t sa = sb + stage * 2 * STG_SZ;
        const uint32_t sbB = sa + STG_SZ;
        const __nv_bfloat16* ga = g_Xs + (size_t)(bm + lr) * 128 + h * 64;
        const __nv_bfloat16* gb = g_Es + (size_t)(bn + lr) * 256 + p * 128 + h * 64;
#pragma unroll
        for (int s = 0; s < 4; s++) {
            cp_async16(sa + sw128((uint32_t)lr * 128 + (ls0 + s) * 16), ga + (ls0 + s) * 8);
            cp_async16(sbB + sw128((uint32_t)lr * 128 + (ls0 + s) * 16), gb + (ls0 + s) * 8);
        }
        CP_COMMIT();
    };

    issue_chunk(0, 0);
    issue_chunk(1, 1);

#pragma unroll 1
    for (int c = 0; c < 4; c++) {
        const int stage = c % 3;
        if (c < 3) { CP_WAIT(1); } else { CP_WAIT(0); }
        __syncthreads();

        const uint32_t sa = sb + stage * 2 * STG_SZ;
        const uint32_t sbB = sa + STG_SZ;
#pragma unroll
        for (int ks = 0; ks < 4; ks++) {
            uint32_t a[2][4];
#pragma unroll
            for (int mt = 0; mt < 2; mt++)
                ldm_x4(a[mt], sa + sw128((uint32_t)(arow + mt * 16) * 128 + ks * 32 + acol));
#pragma unroll
            for (int ntp = 0; ntp < 4; ntp++) {
                uint32_t b[4];
                ldm_x4(b, sbB + sw128((uint32_t)(warp_n * 64 + ntp * 16 + b_lrow) * 128
                                       + ks * 32 + b_lcol));
                mma_bf16(acc[0][2 * ntp],     a[0], b);
                mma_bf16(acc[1][2 * ntp],     a[1], b);
                mma_bf16(acc[0][2 * ntp + 1], a[0], b + 2);
                mma_bf16(acc[1][2 * ntp + 1], a[1], b + 2);
            }
        }
        if (c <= 1) issue_chunk(c + 2, (c + 2) % 3);
    }
    __syncthreads();

    // Epilogue: accum -> padded smem tile -> coalesced fp16 (2*s - esq + OFFS)
    float* tile = (float*)smem;
#pragma unroll
    for (int mt = 0; mt < 2; mt++) {
        const int r = warp_m * 32 + mt * 16 + (lane >> 2);
#pragma unroll
        for (int nt = 0; nt < 8; nt++) {
            const int cb = warp_n * 64 + nt * 8 + 2 * (lane & 3);
            tile[r * 129 + cb]           = acc[mt][nt][0];
            tile[r * 129 + cb + 1]       = acc[mt][nt][1];
            tile[(r + 8) * 129 + cb]     = acc[mt][nt][2];
            tile[(r + 8) * 129 + cb + 1] = acc[mt][nt][3];
        }
    }
    __syncthreads();

#pragma unroll
    for (int i = 0; i < 16; i++) {
        const int lin = tid + i * 256;           // 0..4095
        const int row = lin >> 5;
        const int c4 = (lin & 31) * 4;
        const float4 esq = *(const float4*)(g_esq + bn + c4);
        const float sx = 2.f * tile[row * 129 + c4 + 0] - esq.x + OFFS;
        const float sy = 2.f * tile[row * 129 + c4 + 1] - esq.y + OFFS;
        const float sz = 2.f * tile[row * 129 + c4 + 2] - esq.z + OFFS;
        const float sw = 2.f * tile[row * 129 + c4 + 3] - esq.w + OFFS;
        __half2 h0 = __floats2half2_rn(sx, sy);
        __half2 h1 = __floats2half2_rn(sz, sw);
        uint2 u;
        u.x = *(const uint32_t*)&h0;
        u.y = *(const uint32_t*)&h1;
        *(uint2*)(g_scores16 + (size_t)(bm + row) * KC + bn + c4) = u;
    }
}

// ---------------------------------------------------------------------------
// Kernel 3: per-row argmax (+ exact fp32 rescue) + softmax + class-prob
// partials + outputs. fp16 score loads: 8 x uint4 (8 halves) per row per lane.
// ---------------------------------------------------------------------------
__global__ __launch_bounds__(128) void row_kernel(const float* __restrict__ x,
                                                  const float* __restrict__ embed,
                                                  float* __restrict__ out) {
    __shared__ float cp[4][KC];
    __shared__ int s_cnt[4];
    __shared__ int s_list[4][32];
    const int tid = threadIdx.x;
    const int warp = tid >> 5, lane = tid & 31;

    for (int i = tid; i < 4 * KC; i += 128) (&cp[0][0])[i] = 0.f;
    __syncthreads();

    const int row0 = blockIdx.x * 32;
    float* cpw = cp[warp];

    for (int it = 0; it < 8; it++) {
        const int row = row0 + warp * 8 + it;
        const __half* S = g_scores16 + (size_t)row * KC;

        float v[64];
        float m = -CUDART_INF_F;
        int mi = 0;
#pragma unroll
        for (int j = 0; j < 8; j++) {
            const int kbase = j * 256 + lane * 8;
            const uint4 qq = *(const uint4*)(S + kbase);
            const float2 f0 = __half22float2(*(const __half2*)&qq.x);
            const float2 f1 = __half22float2(*(const __half2*)&qq.y);
            const float2 f2 = __half22float2(*(const __half2*)&qq.z);
            const float2 f3 = __half22float2(*(const __half2*)&qq.w);
            v[8 * j + 0] = f0.x; v[8 * j + 1] = f0.y;
            v[8 * j + 2] = f1.x; v[8 * j + 3] = f1.y;
            v[8 * j + 4] = f2.x; v[8 * j + 5] = f2.y;
            v[8 * j + 6] = f3.x; v[8 * j + 7] = f3.y;
#pragma unroll
            for (int q = 0; q < 8; q++)
                if (v[8 * j + q] > m) { m = v[8 * j + q]; mi = kbase + q; }
        }
#pragma unroll
        for (int off = 16; off > 0; off >>= 1) {
            float om = __shfl_xor_sync(0xffffffffu, m, off);
            int oi = __shfl_xor_sync(0xffffffffu, mi, off);
            if (om > m || (om == m && oi < mi)) { m = om; mi = oi; }
        }

        // Candidate detection for exact rescue (before v[] is overwritten).
        const float thr = m - RESCUE_THR;
        int cnt = 0;
#pragma unroll
        for (int j = 0; j < 64; j++) cnt += (v[j] > thr) ? 1 : 0;
#pragma unroll
        for (int off = 16; off > 0; off >>= 1)
            cnt += __shfl_xor_sync(0xffffffffu, cnt, off);

        if (cnt > 1) {
            if (lane == 0) s_cnt[warp] = 0;
            __syncwarp();
#pragma unroll
            for (int j = 0; j < 64; j++) {
                if (v[j] > thr) {
                    int pos = atomicAdd(&s_cnt[warp], 1);
                    if (pos < 32)
                        s_list[warp][pos] = (j >> 3) * 256 + lane * 8 + (j & 7);
                }
            }
            __syncwarp();
            const int nc = min(s_cnt[warp], 32);
            const float4 xa = *(const float4*)(x + (size_t)row * D + lane * 4);
            float bv = -CUDART_INF_F; int bi = 0x7fffffff;
            for (int t = 0; t < nc; t++) {
                const int cidx = s_list[warp][t];
                const float4 ea = *(const float4*)(embed + (size_t)cidx * D + lane * 4);
                float d = xa.x * ea.x + xa.y * ea.y + xa.z * ea.z + xa.w * ea.w;
#pragma unroll
                for (int off = 16; off > 0; off >>= 1)
                    d += __shfl_xor_sync(0xffffffffu, d, off);
                const float sc = 2.f * d - g_esq[cidx];
                if (sc > bv || (sc == bv && cidx < bi)) { bv = sc; bi = cidx; }
            }
            mi = bi;
        }

        // softmax (approx scores — fine for the loss; OFFS cancels in v - m)
        float s = 0.f;
#pragma unroll
        for (int j = 0; j < 64; j++) {
            float e = __expf((v[j] - m) * TEMP_INV);
            v[j] = e;
            s += e;
        }
#pragma unroll
        for (int off = 16; off > 0; off >>= 1)
            s += __shfl_xor_sync(0xffffffffu, s, off);
        const float inv = 1.f / s;

#pragma unroll
        for (int j = 0; j < 8; j++) {
            float4* p0 = (float4*)(cpw + j * 256 + lane * 8);
            float4 c0 = p0[0];
            c0.x += v[8 * j + 0] * inv; c0.y += v[8 * j + 1] * inv;
            c0.z += v[8 * j + 2] * inv; c0.w += v[8 * j + 3] * inv;
            p0[0] = c0;
            float4 c1 = p0[1];
            c1.x += v[8 * j + 4] * inv; c1.y += v[8 * j + 5] * inv;
            c1.z += v[8 * j + 6] * inv; c1.w += v[8 * j + 7] * inv;
            p0[1] = c1;
        }

        float4 q = *(const float4*)(embed + (size_t)mi * D + lane * 4);
        *(float4*)(out + (size_t)row * D + lane * 4) = q;
        if (lane == 0) out[(size_t)NP * D + row] = (float)mi;
    }

    __syncthreads();
    for (int i = tid; i < KC; i += 128)
        g_part[(size_t)blockIdx.x * KC + i] =
            cp[0][i] + cp[1][i] + cp[2][i] + cp[3][i];
}

// ---------------------------------------------------------------------------
// Kernel 4a/4b: two-stage deterministic reduce of partials
// ---------------------------------------------------------------------------
__global__ __launch_bounds__(256) void reduce1_kernel() {
    const int k = blockIdx.x * 256 + threadIdx.x;
    const int b0 = blockIdx.y * 64;
    float s0 = 0.f, s1 = 0.f, s2 = 0.f, s3 = 0.f;
    for (int b = 0; b < 64; b += 4) {
        s0 += g_part[(size_t)(b0 + b + 0) * KC + k];
        s1 += g_part[(size_t)(b0 + b + 1) * KC + k];
        s2 += g_part[(size_t)(b0 + b + 2) * KC + k];
        s3 += g_part[(size_t)(b0 + b + 3) * KC + k];
    }
    g_part2[blockIdx.y * KC + k] = (s0 + s1) + (s2 + s3);
}

__global__ __launch_bounds__(256) void reduce2_kernel() {
    const int k = blockIdx.x * 256 + threadIdx.x;
    float s = 0.f;
#pragma unroll
    for (int b = 0; b < 16; b++) s += g_part2[b * KC + k];
    g_acc[k] = s;
}

// ---------------------------------------------------------------------------
// Kernel 5: diversity loss
// ---------------------------------------------------------------------------
__global__ __launch_bounds__(256) void loss_kernel(float* __restrict__ out) {
    __shared__ float red[8];
    const int tid = threadIdx.x;
    float t = 0.f;
    for (int k = tid; k < KC; k += 256) {
        float p = g_acc[k] * (1.0f / (float)NP);
        t += p * logf(p + LEPS);
    }
#pragma unroll
    for (int off = 16; off > 0; off >>= 1)
        t += __shfl_xor_sync(0xffffffffu, t, off);
    if ((tid & 31) == 0) red[tid >> 5] = t;
    __syncthreads();
    if (tid < 8) {
        t = red[tid];
#pragma unroll
        for (int off = 4; off > 0; off >>= 1)
            t += __shfl_xor_sync(0x000000ffu, t, off);
        if (tid == 0) out[(size_t)NP * D + NP] = t;
    }
}

// ---------------------------------------------------------------------------
extern "C" void kernel_launch(void* const* d_in, const int* in_sizes, int n_in,
                              void* d_out, int out_size) {
    const float* x = (const float*)d_in[0];
    const float* e = (const float*)d_in[1];
    float* out = (float*)d_out;

    cudaFuncSetAttribute(gemm_kernel, cudaFuncAttributeMaxDynamicSharedMemorySize, GEMM_SMEM);

    split_kernel<<<((NP + KC) * D + 255) / 256, 256>>>(x, e);
    prep_kernel<<<(KC + 255) / 256, 256>>>(e);
    gemm_kernel<<<dim3(KC / 128, NP / 128), 256, GEMM_SMEM>>>();
    row_kernel<<<NP / 32, 128>>>(x, e, out);
    reduce1_kernel<<<dim3(KC / 256, 16), 256>>>();
    reduce2_kernel<<<KC / 256, 256>>>();
    loss_kernel<<<1, 256>>>(out);
}